// round 2
// baseline (speedup 1.0000x reference)
#include <cuda_runtime.h>
#include <math.h>

// Problem constants
#define NB    4
#define HWSZ  4096          // 64*64
#define KDIM  2304          // 256*9

// ---------------------------------------------------------------------------
// Scratch (device globals; allocation inside kernel_launch is forbidden)
// ---------------------------------------------------------------------------
__device__ float g_t1[NB * 256 * HWSZ];     // 16.8 MB
__device__ float g_t2[NB * 256 * HWSZ];     // 16.8 MB
__device__ float g_t3[NB * 432 * HWSZ];     // 28.3 MB
__device__ float g_cols[NB * KDIM * HWSZ];  // 151 MB  (im2col / sampled columns)

// Destination selector for the GEMM kernel (avoids host-side symbol lookup).
#define DST_T1  0
#define DST_T2  1
#define DST_T3  2
#define DST_OUT 3

// ---------------------------------------------------------------------------
// im2col for 3x3, pad=1, stride=1, Cin=256 (or 432 never needed), 64x64.
// cols[b][cin*9+tap][hw] = src[b][cin][y+ki-1][x+kj-1] (0 outside)
// src selected by flag: 0 = external pointer, 1 = g_t1, 2 = g_t2.
// ---------------------------------------------------------------------------
__global__ void im2col_k(const float* __restrict__ ext, int srcsel)
{
    const float* src = (srcsel == 1) ? g_t1 : (srcsel == 2) ? g_t2 : ext;
    int idx = blockIdx.x * 256 + threadIdx.x;       // exact grid: NB*KDIM*HWSZ threads
    int hw   = idx & (HWSZ - 1);
    int t    = idx >> 12;
    int kidx = t % KDIM;
    int b    = t / KDIM;
    int cin  = kidx / 9;
    int tap  = kidx - cin * 9;
    int ki   = tap / 3;
    int kj   = tap - ki * 3;
    int y    = hw >> 6;
    int x    = hw & 63;
    int ys   = y + ki - 1;
    int xs   = x + kj - 1;
    float v = 0.f;
    if ((unsigned)ys < 64u && (unsigned)xs < 64u)
        v = src[((size_t)(b * 256 + cin) << 12) + (ys << 6) + xs];
    g_cols[idx] = v;
}

// ---------------------------------------------------------------------------
// Bilinear sampling of x driven by offsets/mask in g_t3, producing GEMM-ready
// columns: g_cols[b][(g*16+c)*9+k][hw] = bilinear(x[b][g*16+c], ys, xs)*sigmoid(mask)
// Offset layout (matches reference): dy = t3[g*18+2k], dx = t3[g*18+2k+1],
// mask = t3[288 + g*9 + k].
// ---------------------------------------------------------------------------
__global__ void sample_k(const float* __restrict__ x)
{
    const int b  = blockIdx.z;
    const int gk = blockIdx.y;          // 0..143 = g*9 + k
    const int g  = gk / 9;
    const int k  = gk - g * 9;
    const int ki = k / 3;
    const int kj = k - ki * 3;
    const int p  = blockIdx.x * 256 + threadIdx.x;  // 0..4095
    const int y  = p >> 6;
    const int xx = p & 63;

    const float* t3b = g_t3 + (size_t)b * 432 * HWSZ;
    const float dy = t3b[(g * 18 + 2 * k) * HWSZ + p];
    const float dx = t3b[(g * 18 + 2 * k + 1) * HWSZ + p];
    float mv       = t3b[(288 + g * 9 + k) * HWSZ + p];
    mv = 1.f / (1.f + expf(-mv));                   // sigmoid

    const float ys  = (float)(y - 1 + ki) + dy;
    const float xs  = (float)(xx - 1 + kj) + dx;
    const float y0f = floorf(ys);
    const float x0f = floorf(xs);
    const float wy  = ys - y0f;
    const float wx  = xs - x0f;
    const int y0 = (int)y0f;
    const int x0 = (int)x0f;

    const bool vy0 = ((unsigned)y0       < 64u);
    const bool vy1 = ((unsigned)(y0 + 1) < 64u);
    const bool vx0 = ((unsigned)x0       < 64u);
    const bool vx1 = ((unsigned)(x0 + 1) < 64u);

    // fold mask + validity (zero padding) into corner weights
    float w00 = (vy0 && vx0) ? (1.f - wy) * (1.f - wx) * mv : 0.f;
    float w01 = (vy0 && vx1) ? (1.f - wy) * wx         * mv : 0.f;
    float w10 = (vy1 && vx0) ? wy * (1.f - wx)         * mv : 0.f;
    float w11 = (vy1 && vx1) ? wy * wx                 * mv : 0.f;

    const int yc0 = min(max(y0, 0), 63);
    const int yc1 = min(max(y0 + 1, 0), 63);
    const int xc0 = min(max(x0, 0), 63);
    const int xc1 = min(max(x0 + 1, 0), 63);
    const int i00 = (yc0 << 6) + xc0;
    const int i01 = (yc0 << 6) + xc1;
    const int i10 = (yc1 << 6) + xc0;
    const int i11 = (yc1 << 6) + xc1;

    const float* xb = x + ((size_t)b * 256 + g * 16) * HWSZ;
    float* cb = g_cols + ((size_t)b * KDIM + (g * 16) * 9 + k) * HWSZ + p;

#pragma unroll
    for (int c = 0; c < 16; ++c) {
        const float* xc = xb + c * HWSZ;
        float v = w00 * xc[i00] + w01 * xc[i01] + w10 * xc[i10] + w11 * xc[i11];
        cb[(size_t)c * 9 * HWSZ] = v;
    }
}

// ---------------------------------------------------------------------------
// fp32 GEMM:  C[b][m][n] = sum_k A[m][k] * g_cols[b][k][n] + bias[m]   (+SiLU)
// K = 2304, N = 4096 per batch image. Block tile 128x128, thread tile 8x8,
// double-buffered shared memory. Destination chosen device-side via dstsel.
// ---------------------------------------------------------------------------
__global__ void __launch_bounds__(256, 2)
gemm_k(const float* __restrict__ A, const float* __restrict__ bias,
       float* __restrict__ extC, int M, int act, int dstsel)
{
    __shared__ float As[2][8][128];   // [buf][kk][m]
    __shared__ float Bs[2][8][128];   // [buf][kk][n]

    float* C = (dstsel == DST_T1) ? g_t1
             : (dstsel == DST_T2) ? g_t2
             : (dstsel == DST_T3) ? g_t3 : extC;

    const float* Bb = g_cols + (size_t)blockIdx.z * (KDIM * HWSZ);
    float* Cb = C + (size_t)blockIdx.z * M * HWSZ;

    const int tid = threadIdx.x;
    const int tx  = tid & 15;
    const int ty  = tid >> 4;
    const int n0  = blockIdx.x * 128;
    const int m0  = blockIdx.y * 128;

    const int a_row = m0 + (tid >> 1);       // 128 rows, 2 threads per row
    const int a_col = (tid & 1) * 4;         // float4 within the 8-wide K chunk
    const int b_row = tid >> 5;              // 8 K-rows, 32 threads per row
    const int b_col = (tid & 31) * 4;        // float4 within 128-wide N

    float acc[8][8];
#pragma unroll
    for (int i = 0; i < 8; ++i)
#pragma unroll
        for (int j = 0; j < 8; ++j) acc[i][j] = 0.f;

    // preload chunk 0
    float4 va = make_float4(0.f, 0.f, 0.f, 0.f);
    if (a_row < M) va = *(const float4*)(A + (size_t)a_row * KDIM + a_col);
    float4 vb = *(const float4*)(Bb + (size_t)b_row * HWSZ + n0 + b_col);
    As[0][a_col + 0][tid >> 1] = va.x;
    As[0][a_col + 1][tid >> 1] = va.y;
    As[0][a_col + 2][tid >> 1] = va.z;
    As[0][a_col + 3][tid >> 1] = va.w;
    *(float4*)(&Bs[0][b_row][b_col]) = vb;
    __syncthreads();

    const int nCh = KDIM / 8;   // 288
    for (int t = 0; t < nCh; ++t) {
        const int buf = t & 1;
        const bool more = (t + 1 < nCh);
        float4 na = make_float4(0.f, 0.f, 0.f, 0.f);
        float4 nb = make_float4(0.f, 0.f, 0.f, 0.f);
        if (more) {
            const int k0 = (t + 1) * 8;
            if (a_row < M) na = *(const float4*)(A + (size_t)a_row * KDIM + k0 + a_col);
            nb = *(const float4*)(Bb + (size_t)(k0 + b_row) * HWSZ + n0 + b_col);
        }

        float af[8], bf[8];
#pragma unroll
        for (int kk = 0; kk < 8; ++kk) {
            *(float4*)(af)     = *(const float4*)(&As[buf][kk][ty * 4]);
            *(float4*)(af + 4) = *(const float4*)(&As[buf][kk][ty * 4 + 64]);
            *(float4*)(bf)     = *(const float4*)(&Bs[buf][kk][tx * 4]);
            *(float4*)(bf + 4) = *(const float4*)(&Bs[buf][kk][tx * 4 + 64]);
#pragma unroll
            for (int i = 0; i < 8; ++i)
#pragma unroll
                for (int j = 0; j < 8; ++j)
                    acc[i][j] = fmaf(af[i], bf[j], acc[i][j]);
        }

        if (more) {
            As[buf ^ 1][a_col + 0][tid >> 1] = na.x;
            As[buf ^ 1][a_col + 1][tid >> 1] = na.y;
            As[buf ^ 1][a_col + 2][tid >> 1] = na.z;
            As[buf ^ 1][a_col + 3][tid >> 1] = na.w;
            *(float4*)(&Bs[buf ^ 1][b_row][b_col]) = nb;
            __syncthreads();
        }
    }

    // epilogue: bias (+ optional SiLU), vectorized stores
#pragma unroll
    for (int i = 0; i < 8; ++i) {
        const int r = m0 + ((i < 4) ? (ty * 4 + i) : (64 + ty * 4 + i - 4));
        if (r < M) {
            const float bv = bias[r];
            float o[8];
#pragma unroll
            for (int j = 0; j < 8; ++j) {
                float v = acc[i][j] + bv;
                if (act) v = v / (1.f + expf(-v));   // SiLU
                o[j] = v;
            }
            *(float4*)(Cb + (size_t)r * HWSZ + n0 + tx * 4)      = *(float4*)(o);
            *(float4*)(Cb + (size_t)r * HWSZ + n0 + 64 + tx * 4) = *(float4*)(o + 4);
        }
    }
}

// ---------------------------------------------------------------------------
// Launch: conv1(SiLU) -> conv2(SiLU) -> conv3 -> sample -> deform GEMM
// Only kernel launches here — fully graph-capturable, no runtime API calls.
// ---------------------------------------------------------------------------
extern "C" void kernel_launch(void* const* d_in, const int* in_sizes, int n_in,
                              void* d_out, int out_size)
{
    (void)in_sizes; (void)n_in; (void)out_size;
    const float* x      = (const float*)d_in[0];
    const float* offf   = (const float*)d_in[1];
    const float* weight = (const float*)d_in[2];
    const float* bias   = (const float*)d_in[3];
    const float* w1     = (const float*)d_in[4];
    const float* b1     = (const float*)d_in[5];
    const float* w2     = (const float*)d_in[6];
    const float* b2     = (const float*)d_in[7];
    const float* w3     = (const float*)d_in[8];
    const float* b3     = (const float*)d_in[9];
    float* out = (float*)d_out;

    const int IMB = (NB * KDIM * HWSZ) / 256;   // exact
    dim3 gemmG(32, 2, NB);      // M=256
    dim3 gemmG3(32, 4, NB);     // M=432

    im2col_k<<<IMB, 256>>>(offf, 0);
    gemm_k<<<gemmG, 256>>>(w1, b1, nullptr, 256, 1, DST_T1);

    im2col_k<<<IMB, 256>>>(nullptr, 1);
    gemm_k<<<gemmG, 256>>>(w2, b2, nullptr, 256, 1, DST_T2);

    im2col_k<<<IMB, 256>>>(nullptr, 2);
    gemm_k<<<gemmG3, 256>>>(w3, b3, nullptr, 432, 0, DST_T3);

    sample_k<<<dim3(16, 144, NB), 256>>>(x);
    gemm_k<<<gemmG, 256>>>(weight, bias, out, 256, 0, DST_OUT);
}

// round 4
// speedup vs baseline: 2.1143x; 2.1143x over previous
#include <cuda_runtime.h>
#include <cuda_bf16.h>
#include <math.h>
#include <stdint.h>

#define NB    4
#define HWSZ  4096
#define KDIM  2304
#define NCH   (KDIM / 32)      // 72 k-chunks of 32

// ---------------------------------------------------------------------------
// Scratch (device globals)
// ---------------------------------------------------------------------------
__device__ float g_t1[NB * 256 * HWSZ];                       // fp32 activations
__device__ float g_t2[NB * 256 * HWSZ];
__device__ float g_t3[NB * 432 * HWSZ];
__device__ __nv_bfloat16 g_colsh[(size_t)NB * KDIM * HWSZ];   // B hi plane (75.5MB)
__device__ __nv_bfloat16 g_colsl[(size_t)NB * KDIM * HWSZ];   // B lo plane
__device__ __nv_bfloat16 g_wh[1280 * KDIM];                   // packed weights hi
__device__ __nv_bfloat16 g_wl[1280 * KDIM];                   // packed weights lo

#define DST_T1  0
#define DST_T2  1
#define DST_T3  2
#define DST_OUT 3

// ---------------------------------------------------------------------------
// PTX helpers (family-common: valid on target sm_100)
// ---------------------------------------------------------------------------
static __device__ __forceinline__ uint32_t smem_u32(const void* p) {
    uint32_t a;
    asm("{ .reg .u64 t; cvta.to.shared.u64 t, %1; cvt.u32.u64 %0, t; }" : "=r"(a) : "l"(p));
    return a;
}
#define CP16(dst, src) \
    asm volatile("cp.async.cg.shared.global [%0], [%1], 16;" :: "r"(dst), "l"(src))
#define CP_COMMIT()  asm volatile("cp.async.commit_group;" ::: "memory")
#define CP_WAIT1()   asm volatile("cp.async.wait_group 1;" ::: "memory")
#define CP_WAIT0()   asm volatile("cp.async.wait_group 0;" ::: "memory")

#define LDSM_X4(r, addr) \
    asm volatile("ldmatrix.sync.aligned.m8n8.x4.shared.b16 {%0,%1,%2,%3}, [%4];" \
        : "=r"((r)[0]), "=r"((r)[1]), "=r"((r)[2]), "=r"((r)[3]) : "r"(addr))
#define LDSM_X2T(r, addr) \
    asm volatile("ldmatrix.sync.aligned.m8n8.x2.trans.shared.b16 {%0,%1}, [%2];" \
        : "=r"((r)[0]), "=r"((r)[1]) : "r"(addr))

#define MMA_BF16(d, a, b) \
    asm volatile("mma.sync.aligned.m16n8k16.row.col.f32.bf16.bf16.f32 " \
        "{%0,%1,%2,%3}, {%4,%5,%6,%7}, {%8,%9}, {%0,%1,%2,%3};" \
        : "+f"((d)[0]), "+f"((d)[1]), "+f"((d)[2]), "+f"((d)[3]) \
        : "r"((a)[0]), "r"((a)[1]), "r"((a)[2]), "r"((a)[3]), "r"((b)[0]), "r"((b)[1]))

static __device__ __forceinline__ void split_store(float v, __nv_bfloat16* ph,
                                                   __nv_bfloat16* pl) {
    __nv_bfloat16 h = __float2bfloat16_rn(v);
    *ph = h;
    *pl = __float2bfloat16_rn(v - __bfloat162float(h));
}

// ---------------------------------------------------------------------------
// Weight pre-convert: pack w1|w2|w3(padded to 512 rows)|weight into bf16 hi/lo
// table of 1280 rows x 2304.
// ---------------------------------------------------------------------------
__global__ void convw_k(const float* __restrict__ w1, const float* __restrict__ w2,
                        const float* __restrict__ w3, const float* __restrict__ wm)
{
    int idx = blockIdx.x * 256 + threadIdx.x;       // 0 .. 1280*2304-1
    int row = idx / KDIM;
    int col = idx - row * KDIM;
    float v = 0.f;
    if (row < 256)       v = w1[row * KDIM + col];
    else if (row < 512)  v = w2[(row - 256) * KDIM + col];
    else if (row < 1024) { int r = row - 512; if (r < 432) v = w3[r * KDIM + col]; }
    else                 v = wm[(row - 1024) * KDIM + col];
    split_store(v, &g_wh[idx], &g_wl[idx]);
}

// ---------------------------------------------------------------------------
// im2col -> bf16 hi/lo planes. src: 0=ext fp32, 1=g_t1, 2=g_t2
// ---------------------------------------------------------------------------
__global__ void im2col_k(const float* __restrict__ ext, int srcsel)
{
    const float* src = (srcsel == 1) ? g_t1 : (srcsel == 2) ? g_t2 : ext;
    int idx = blockIdx.x * 256 + threadIdx.x;
    int hw   = idx & (HWSZ - 1);
    int t    = idx >> 12;
    int kidx = t % KDIM;
    int b    = t / KDIM;
    int cin  = kidx / 9;
    int tap  = kidx - cin * 9;
    int ki   = tap / 3;
    int kj   = tap - ki * 3;
    int y    = hw >> 6;
    int x    = hw & 63;
    int ys   = y + ki - 1;
    int xs   = x + kj - 1;
    float v = 0.f;
    if ((unsigned)ys < 64u && (unsigned)xs < 64u)
        v = src[((size_t)(b * 256 + cin) << 12) + (ys << 6) + xs];
    split_store(v, &g_colsh[idx], &g_colsl[idx]);
}

// ---------------------------------------------------------------------------
// Deformable bilinear sampling -> bf16 hi/lo planes
// ---------------------------------------------------------------------------
__global__ void sample_k(const float* __restrict__ x)
{
    const int b  = blockIdx.z;
    const int gk = blockIdx.y;
    const int g  = gk / 9;
    const int k  = gk - g * 9;
    const int ki = k / 3;
    const int kj = k - ki * 3;
    const int p  = blockIdx.x * 256 + threadIdx.x;
    const int y  = p >> 6;
    const int xx = p & 63;

    const float* t3b = g_t3 + (size_t)b * 432 * HWSZ;
    const float dy = t3b[(g * 18 + 2 * k) * HWSZ + p];
    const float dx = t3b[(g * 18 + 2 * k + 1) * HWSZ + p];
    float mv       = t3b[(288 + g * 9 + k) * HWSZ + p];
    mv = 1.f / (1.f + expf(-mv));

    const float ys  = (float)(y - 1 + ki) + dy;
    const float xs  = (float)(xx - 1 + kj) + dx;
    const float y0f = floorf(ys);
    const float x0f = floorf(xs);
    const float wy  = ys - y0f;
    const float wx  = xs - x0f;
    const int y0 = (int)y0f;
    const int x0 = (int)x0f;

    const bool vy0 = ((unsigned)y0       < 64u);
    const bool vy1 = ((unsigned)(y0 + 1) < 64u);
    const bool vx0 = ((unsigned)x0       < 64u);
    const bool vx1 = ((unsigned)(x0 + 1) < 64u);

    float w00 = (vy0 && vx0) ? (1.f - wy) * (1.f - wx) * mv : 0.f;
    float w01 = (vy0 && vx1) ? (1.f - wy) * wx         * mv : 0.f;
    float w10 = (vy1 && vx0) ? wy * (1.f - wx)         * mv : 0.f;
    float w11 = (vy1 && vx1) ? wy * wx                 * mv : 0.f;

    const int yc0 = min(max(y0, 0), 63);
    const int yc1 = min(max(y0 + 1, 0), 63);
    const int xc0 = min(max(x0, 0), 63);
    const int xc1 = min(max(x0 + 1, 0), 63);
    const int i00 = (yc0 << 6) + xc0;
    const int i01 = (yc0 << 6) + xc1;
    const int i10 = (yc1 << 6) + xc0;
    const int i11 = (yc1 << 6) + xc1;

    const float* xb = x + ((size_t)b * 256 + g * 16) * HWSZ;
    const size_t base = ((size_t)b * KDIM + (g * 16) * 9 + k) * HWSZ + p;

#pragma unroll
    for (int c = 0; c < 16; ++c) {
        const float* xc = xb + c * HWSZ;
        float v = w00 * xc[i00] + w01 * xc[i01] + w10 * xc[i10] + w11 * xc[i11];
        size_t o = base + (size_t)c * 9 * HWSZ;
        split_store(v, &g_colsh[o], &g_colsl[o]);
    }
}

// ---------------------------------------------------------------------------
// HMMA bf16-split GEMM:
//   C[b][m][n] = sum_k W[aoff+m][k] * cols[b][k][n] + bias[m]  (+SiLU)
// CTA tile 128x128x32, 8 warps (2m x 4n), warp tile 64x32, mma m16n8k16,
// 3 products per hi/lo pair, cp.async double buffer.
// SMEM: A [buf][plane][128m][80B-pitch], B [buf][plane][32k][272B-pitch]
// ---------------------------------------------------------------------------
#define A_P   10240     // plane size: 128*80
#define A_B   20480     // buf size: 2 planes
#define B_ST  40960
#define B_P   8704      // 32*272
#define B_B   17408
#define SMEM_TOT 75776

__global__ void __launch_bounds__(256)
gemm_tc(int aoff, const float* __restrict__ bias, float* __restrict__ extC,
        int M, int act, int dstsel)
{
    extern __shared__ char smem[];
    const uint32_t sb = smem_u32(smem);
    const int tid  = threadIdx.x;
    const int lane = tid & 31;
    const int wid  = tid >> 5;
    const int wm   = wid >> 2;          // 0..1
    const int wn   = wid & 3;           // 0..3
    const int m0   = blockIdx.x * 128;
    const int n0   = blockIdx.y * 128;
    const int b    = blockIdx.z;

    float* C = (dstsel == DST_T1) ? g_t1
             : (dstsel == DST_T2) ? g_t2
             : (dstsel == DST_T3) ? g_t3 : extC;
    float* Cb = C + (size_t)b * M * HWSZ;

    const __nv_bfloat16* gAh = g_wh + (size_t)(aoff + m0) * KDIM;
    const __nv_bfloat16* gAl = g_wl + (size_t)(aoff + m0) * KDIM;
    const __nv_bfloat16* gBh = g_colsh + (size_t)b * KDIM * HWSZ;
    const __nv_bfloat16* gBl = g_colsl + (size_t)b * KDIM * HWSZ;

    // per-thread cp.async mapping
    const int am0 = tid >> 2, akc = tid & 3;          // A: +256 -> m += 64
    const int bk0 = tid >> 4, bnc = tid & 15;         // B: +256 -> k += 16

    auto issue = [&](int t, int buf) {
        const int k0 = t * 32;
#pragma unroll
        for (int pl = 0; pl < 2; ++pl) {
            const __nv_bfloat16* g = pl ? gAl : gAh;
#pragma unroll
            for (int it = 0; it < 2; ++it) {
                int m = am0 + it * 64;
                uint32_t dst = sb + buf * A_B + pl * A_P + m * 80 + akc * 16;
                CP16(dst, g + (size_t)m * KDIM + k0 + akc * 8);
            }
        }
#pragma unroll
        for (int pl = 0; pl < 2; ++pl) {
            const __nv_bfloat16* g = pl ? gBl : gBh;
#pragma unroll
            for (int it = 0; it < 2; ++it) {
                int kk = bk0 + it * 16;
                uint32_t dst = sb + B_ST + buf * B_B + pl * B_P + kk * 272 + bnc * 16;
                CP16(dst, g + (size_t)(k0 + kk) * HWSZ + n0 + bnc * 8);
            }
        }
        CP_COMMIT();
    };

    float acc[4][4][4];
#pragma unroll
    for (int i = 0; i < 4; ++i)
#pragma unroll
        for (int j = 0; j < 4; ++j)
#pragma unroll
            for (int q = 0; q < 4; ++q) acc[i][j][q] = 0.f;

    issue(0, 0);

    for (int t = 0; t < NCH; ++t) {
        const int buf = t & 1;
        const bool more = (t + 1 < NCH);
        if (more) { issue(t + 1, buf ^ 1); CP_WAIT1(); }
        else      { CP_WAIT0(); }
        __syncthreads();

        const uint32_t aBase = sb + buf * A_B;
        const uint32_t bBase = sb + B_ST + buf * B_B;
#pragma unroll
        for (int s = 0; s < 2; ++s) {
            uint32_t ah[4][4], al[4][4], bh[4][2], bl[4][2];
            const uint32_t arow = (uint32_t)(wm * 64 + (lane & 15));
            const uint32_t acol = (uint32_t)(s * 32 + (lane >> 4) * 16);
#pragma unroll
            for (int i = 0; i < 4; ++i) {
                uint32_t off = (arow + i * 16) * 80 + acol;
                LDSM_X4(ah[i], aBase + off);
                LDSM_X4(al[i], aBase + A_P + off);
            }
            const uint32_t brow = (uint32_t)(s * 16 + (lane & 15));
#pragma unroll
            for (int j = 0; j < 4; ++j) {
                uint32_t off = brow * 272 + (uint32_t)(wn * 64 + j * 16);
                LDSM_X2T(bh[j], bBase + off);
                LDSM_X2T(bl[j], bBase + B_P + off);
            }
#pragma unroll
            for (int i = 0; i < 4; ++i)
#pragma unroll
                for (int j = 0; j < 4; ++j) {
                    MMA_BF16(acc[i][j], ah[i], bh[j]);
                    MMA_BF16(acc[i][j], ah[i], bl[j]);
                    MMA_BF16(acc[i][j], al[i], bh[j]);
                }
        }
        __syncthreads();
    }

    // epilogue: bias (+SiLU), float2 stores
#pragma unroll
    for (int i = 0; i < 4; ++i) {
        const int r0 = m0 + wm * 64 + i * 16 + (lane >> 2);
#pragma unroll
        for (int h = 0; h < 2; ++h) {
            const int r = r0 + h * 8;
            if (r < M) {
                const float bv = bias[r];
                float* dst = Cb + (size_t)r * HWSZ + n0 + wn * 32 + (lane & 3) * 2;
#pragma unroll
                for (int j = 0; j < 4; ++j) {
                    float v0 = acc[i][j][h * 2 + 0] + bv;
                    float v1 = acc[i][j][h * 2 + 1] + bv;
                    if (act) {
                        v0 = v0 / (1.f + expf(-v0));
                        v1 = v1 / (1.f + expf(-v1));
                    }
                    *(float2*)(dst + j * 8) = make_float2(v0, v1);
                }
            }
        }
    }
}

// ---------------------------------------------------------------------------
// Launch sequence
// ---------------------------------------------------------------------------
extern "C" void kernel_launch(void* const* d_in, const int* in_sizes, int n_in,
                              void* d_out, int out_size)
{
    (void)in_sizes; (void)n_in; (void)out_size;
    const float* x      = (const float*)d_in[0];
    const float* offf   = (const float*)d_in[1];
    const float* weight = (const float*)d_in[2];
    const float* bias   = (const float*)d_in[3];
    const float* w1     = (const float*)d_in[4];
    const float* b1     = (const float*)d_in[5];
    const float* w2     = (const float*)d_in[6];
    const float* b2     = (const float*)d_in[7];
    const float* w3     = (const float*)d_in[8];
    const float* b3     = (const float*)d_in[9];
    float* out = (float*)d_out;

    cudaFuncSetAttribute(gemm_tc, cudaFuncAttributeMaxDynamicSharedMemorySize, SMEM_TOT);

    const int IMB = (NB * KDIM * HWSZ) / 256;
    dim3 g256(2, 32, NB);       // (mtiles, ntiles, batch)
    dim3 g432(4, 32, NB);

    convw_k<<<(1280 * KDIM) / 256, 256>>>(w1, w2, w3, weight);

    im2col_k<<<IMB, 256>>>(offf, 0);
    gemm_tc<<<g256, 256, SMEM_TOT>>>(0,    b1,   nullptr, 256, 1, DST_T1);

    im2col_k<<<IMB, 256>>>(nullptr, 1);
    gemm_tc<<<g256, 256, SMEM_TOT>>>(256,  b2,   nullptr, 256, 1, DST_T2);

    im2col_k<<<IMB, 256>>>(nullptr, 2);
    gemm_tc<<<g432, 256, SMEM_TOT>>>(512,  b3,   nullptr, 432, 0, DST_T3);

    sample_k<<<dim3(16, 144, NB), 256>>>(x);
    gemm_tc<<<g256, 256, SMEM_TOT>>>(1024, bias, out,     256, 0, DST_OUT);
}

// round 5
// speedup vs baseline: 3.1334x; 1.4820x over previous
#include <cuda_runtime.h>
#include <cuda_fp16.h>
#include <math.h>
#include <stdint.h>

#define NB    4
#define HWSZ  4096
#define KDIM  2304
#define NCH   (KDIM / 32)      // 72 k-chunks of 32

// ---------------------------------------------------------------------------
// Scratch (device globals)
// ---------------------------------------------------------------------------
__device__ float g_t1[NB * 256 * HWSZ];                 // fp32 activations
__device__ float g_t2[NB * 256 * HWSZ];
__device__ float g_t3[NB * 432 * HWSZ];
__device__ __half g_cols[(size_t)NB * KDIM * HWSZ];     // B fp16 plane (75.5MB)
__device__ __half g_wh[1280 * KDIM];                    // packed weights hi
__device__ __half g_wl[1280 * KDIM];                    // packed weights lo

#define DST_T1  0
#define DST_T2  1
#define DST_T3  2
#define DST_OUT 3

// ---------------------------------------------------------------------------
// PTX helpers (family-common, valid on target sm_100)
// ---------------------------------------------------------------------------
static __device__ __forceinline__ uint32_t smem_u32(const void* p) {
    uint32_t a;
    asm("{ .reg .u64 t; cvta.to.shared.u64 t, %1; cvt.u32.u64 %0, t; }" : "=r"(a) : "l"(p));
    return a;
}
#define CP16(dst, src) \
    asm volatile("cp.async.cg.shared.global [%0], [%1], 16;" :: "r"(dst), "l"(src))
#define CP_COMMIT()  asm volatile("cp.async.commit_group;" ::: "memory")
#define CP_WAIT1()   asm volatile("cp.async.wait_group 1;" ::: "memory")
#define CP_WAIT0()   asm volatile("cp.async.wait_group 0;" ::: "memory")

#define LDSM_X4(r, addr) \
    asm volatile("ldmatrix.sync.aligned.m8n8.x4.shared.b16 {%0,%1,%2,%3}, [%4];" \
        : "=r"((r)[0]), "=r"((r)[1]), "=r"((r)[2]), "=r"((r)[3]) : "r"(addr))
#define LDSM_X2T(r, addr) \
    asm volatile("ldmatrix.sync.aligned.m8n8.x2.trans.shared.b16 {%0,%1}, [%2];" \
        : "=r"((r)[0]), "=r"((r)[1]) : "r"(addr))

#define MMA_F16(d, a, b) \
    asm volatile("mma.sync.aligned.m16n8k16.row.col.f32.f16.f16.f32 " \
        "{%0,%1,%2,%3}, {%4,%5,%6,%7}, {%8,%9}, {%0,%1,%2,%3};" \
        : "+f"((d)[0]), "+f"((d)[1]), "+f"((d)[2]), "+f"((d)[3]) \
        : "r"((a)[0]), "r"((a)[1]), "r"((a)[2]), "r"((a)[3]), "r"((b)[0]), "r"((b)[1]))

// ---------------------------------------------------------------------------
// Weight pre-convert: pack w1|w2|w3(padded to 512)|weight into fp16 hi/lo
// (1280 rows x 2304). A-split keeps weight error ~2^-22.
// ---------------------------------------------------------------------------
__global__ void convw_k(const float* __restrict__ w1, const float* __restrict__ w2,
                        const float* __restrict__ w3, const float* __restrict__ wm)
{
    int idx = blockIdx.x * 256 + threadIdx.x;       // 0 .. 1280*2304-1
    int row = idx / KDIM;
    int col = idx - row * KDIM;
    float v = 0.f;
    if (row < 256)       v = w1[row * KDIM + col];
    else if (row < 512)  v = w2[(row - 256) * KDIM + col];
    else if (row < 1024) { int r = row - 512; if (r < 432) v = w3[r * KDIM + col]; }
    else                 v = wm[(row - 1024) * KDIM + col];
    __half h = __float2half_rn(v);
    g_wh[idx] = h;
    g_wl[idx] = __float2half_rn(v - __half2float(h));
}

// ---------------------------------------------------------------------------
// im2col -> fp16 plane, 8 elements (one 16B store) per thread.
// src: 0=ext fp32, 1=g_t1, 2=g_t2
// ---------------------------------------------------------------------------
__global__ void im2col_k(const float* __restrict__ ext, int srcsel)
{
    const float* src = (srcsel == 1) ? g_t1 : (srcsel == 2) ? g_t2 : ext;
    int idx  = blockIdx.x * 256 + threadIdx.x;
    int e0   = idx * 8;
    int hw   = e0 & (HWSZ - 1);
    int t    = e0 >> 12;
    int kidx = t % KDIM;
    int b    = t / KDIM;
    int cin  = kidx / 9;
    int tap  = kidx - cin * 9;
    int ki   = tap / 3;
    int kj   = tap - ki * 3;
    int y    = hw >> 6;
    int x0   = hw & 63;
    int ys   = y + ki - 1;
    const bool rowok = ((unsigned)ys < 64u);
    const float* row = src + ((size_t)(b * 256 + cin) << 12) + (ys << 6);

    __half h[8];
#pragma unroll
    for (int e = 0; e < 8; ++e) {
        int xs = x0 + e + kj - 1;
        float v = (rowok && (unsigned)xs < 64u) ? row[xs] : 0.f;
        h[e] = __float2half_rn(v);
    }
    *(uint4*)&g_cols[e0] = *(uint4*)h;
}

// ---------------------------------------------------------------------------
// Deformable bilinear sampling -> fp16 plane
// ---------------------------------------------------------------------------
__global__ void sample_k(const float* __restrict__ x)
{
    const int b  = blockIdx.z;
    const int gk = blockIdx.y;
    const int g  = gk / 9;
    const int k  = gk - g * 9;
    const int ki = k / 3;
    const int kj = k - ki * 3;
    const int p  = blockIdx.x * 256 + threadIdx.x;
    const int y  = p >> 6;
    const int xx = p & 63;

    const float* t3b = g_t3 + (size_t)b * 432 * HWSZ;
    const float dy = t3b[(g * 18 + 2 * k) * HWSZ + p];
    const float dx = t3b[(g * 18 + 2 * k + 1) * HWSZ + p];
    float mv       = t3b[(288 + g * 9 + k) * HWSZ + p];
    mv = 1.f / (1.f + expf(-mv));

    const float ys  = (float)(y - 1 + ki) + dy;
    const float xs  = (float)(xx - 1 + kj) + dx;
    const float y0f = floorf(ys);
    const float x0f = floorf(xs);
    const float wy  = ys - y0f;
    const float wx  = xs - x0f;
    const int y0 = (int)y0f;
    const int x0 = (int)x0f;

    const bool vy0 = ((unsigned)y0       < 64u);
    const bool vy1 = ((unsigned)(y0 + 1) < 64u);
    const bool vx0 = ((unsigned)x0       < 64u);
    const bool vx1 = ((unsigned)(x0 + 1) < 64u);

    float w00 = (vy0 && vx0) ? (1.f - wy) * (1.f - wx) * mv : 0.f;
    float w01 = (vy0 && vx1) ? (1.f - wy) * wx         * mv : 0.f;
    float w10 = (vy1 && vx0) ? wy * (1.f - wx)         * mv : 0.f;
    float w11 = (vy1 && vx1) ? wy * wx                 * mv : 0.f;

    const int yc0 = min(max(y0, 0), 63);
    const int yc1 = min(max(y0 + 1, 0), 63);
    const int xc0 = min(max(x0, 0), 63);
    const int xc1 = min(max(x0 + 1, 0), 63);
    const int i00 = (yc0 << 6) + xc0;
    const int i01 = (yc0 << 6) + xc1;
    const int i10 = (yc1 << 6) + xc0;
    const int i11 = (yc1 << 6) + xc1;

    const float* xb = x + ((size_t)b * 256 + g * 16) * HWSZ;
    const size_t base = ((size_t)b * KDIM + (g * 16) * 9 + k) * HWSZ + p;

#pragma unroll
    for (int c = 0; c < 16; ++c) {
        const float* xc = xb + c * HWSZ;
        float v = w00 * xc[i00] + w01 * xc[i01] + w10 * xc[i10] + w11 * xc[i11];
        g_cols[base + (size_t)c * 9 * HWSZ] = __float2half_rn(v);
    }
}

// ---------------------------------------------------------------------------
// HMMA fp16-split GEMM, CTA tile 256m x 128n x 32k (2 m-subtiles share B):
//   C[b][m][n] = sum_k W[aoff+m][k] * cols[b][k][n] + bias[m]  (+SiLU)
// 8 warps (2m x 4n per msub), warp tile 64x32, mma m16n8k16 fp16,
// 2 products (Ahi*B + Alo*B), cp.async double buffer; B read ONCE per stage.
// SMEM: A [buf][msub][plane][128m][80B], B [buf][32k][272B]
// ---------------------------------------------------------------------------
#define A_PL   10240     // 128*80
#define A_MS   20480     // 2 planes
#define A_BUF  40960     // 2 msub
#define B_ST   81920     // after 2 A bufs
#define B_BUF  8704      // 32*272
#define SMEM_TOT (B_ST + 2 * B_BUF)   // 99328

__global__ void __launch_bounds__(256, 1)
gemm_tc(int aoff, const float* __restrict__ bias, float* __restrict__ extC,
        int M, int act, int dstsel)
{
    extern __shared__ char smem[];
    const uint32_t sb = smem_u32(smem);
    const int tid  = threadIdx.x;
    const int lane = tid & 31;
    const int wid  = tid >> 5;
    const int wm   = wid >> 2;          // 0..1
    const int wn   = wid & 3;           // 0..3
    const int m0   = blockIdx.x * 256;
    const int n0   = blockIdx.y * 128;
    const int b    = blockIdx.z;

    float* C = (dstsel == DST_T1) ? g_t1
             : (dstsel == DST_T2) ? g_t2
             : (dstsel == DST_T3) ? g_t3 : extC;
    float* Cb = C + (size_t)b * M * HWSZ;

    const __half* gAh = g_wh + (size_t)(aoff + m0) * KDIM;
    const __half* gAl = g_wl + (size_t)(aoff + m0) * KDIM;
    const __half* gB  = g_cols + (size_t)b * KDIM * HWSZ;

    // cp.async mappings
    const int arow0 = tid >> 2, akc = tid & 3;     // A: 64 rows x 4 chunks
    const int bk0   = tid >> 4, bnc = tid & 15;    // B: 16 k x 16 chunks

    auto issue = [&](int t, int buf) {
        const int k0 = t * 32;
#pragma unroll
        for (int ms = 0; ms < 2; ++ms)
#pragma unroll
            for (int pl = 0; pl < 2; ++pl) {
                const __half* g = pl ? gAl : gAh;
#pragma unroll
                for (int it = 0; it < 2; ++it) {
                    int m = arow0 + it * 64;
                    uint32_t dst = sb + buf * A_BUF + ms * A_MS + pl * A_PL + m * 80 + akc * 16;
                    CP16(dst, g + (size_t)(ms * 128 + m) * KDIM + k0 + akc * 8);
                }
            }
#pragma unroll
        for (int it = 0; it < 2; ++it) {
            int kk = bk0 + it * 16;
            uint32_t dst = sb + B_ST + buf * B_BUF + kk * 272 + bnc * 16;
            CP16(dst, gB + (size_t)(k0 + kk) * HWSZ + n0 + bnc * 8);
        }
        CP_COMMIT();
    };

    float acc[2][4][4][4];
#pragma unroll
    for (int ms = 0; ms < 2; ++ms)
#pragma unroll
        for (int i = 0; i < 4; ++i)
#pragma unroll
            for (int j = 0; j < 4; ++j)
#pragma unroll
                for (int q = 0; q < 4; ++q) acc[ms][i][j][q] = 0.f;

    issue(0, 0);

    for (int t = 0; t < NCH; ++t) {
        const int buf = t & 1;
        const bool more = (t + 1 < NCH);
        if (more) { issue(t + 1, buf ^ 1); CP_WAIT1(); }
        else      { CP_WAIT0(); }
        __syncthreads();

        const uint32_t aB = sb + buf * A_BUF;
        const uint32_t bB = sb + B_ST + buf * B_BUF;
#pragma unroll
        for (int s = 0; s < 2; ++s) {
            uint32_t bf[4][2];
            const uint32_t brow = (uint32_t)(s * 16 + (lane & 15));
#pragma unroll
            for (int j = 0; j < 4; ++j)
                LDSM_X2T(bf[j], bB + brow * 272 + (uint32_t)(wn * 64 + j * 16));

            const uint32_t arow = (uint32_t)(wm * 64 + (lane & 15));
            const uint32_t acol = (uint32_t)(s * 32 + (lane >> 4) * 16);
#pragma unroll
            for (int ms = 0; ms < 2; ++ms) {
                uint32_t ah[4][4], al[4][4];
#pragma unroll
                for (int i = 0; i < 4; ++i) {
                    uint32_t off = ms * A_MS + (arow + i * 16) * 80 + acol;
                    LDSM_X4(ah[i], aB + off);
                    LDSM_X4(al[i], aB + A_PL + off);
                }
#pragma unroll
                for (int i = 0; i < 4; ++i)
#pragma unroll
                    for (int j = 0; j < 4; ++j) {
                        MMA_F16(acc[ms][i][j], ah[i], bf[j]);
                        MMA_F16(acc[ms][i][j], al[i], bf[j]);
                    }
            }
        }
        __syncthreads();
    }

    // epilogue: bias (+SiLU), float2 stores
#pragma unroll
    for (int ms = 0; ms < 2; ++ms)
#pragma unroll
        for (int i = 0; i < 4; ++i) {
            const int r0 = m0 + ms * 128 + wm * 64 + i * 16 + (lane >> 2);
#pragma unroll
            for (int h = 0; h < 2; ++h) {
                const int r = r0 + h * 8;
                if (r < M) {
                    const float bv = bias[r];
                    float* dst = Cb + (size_t)r * HWSZ + n0 + wn * 32 + (lane & 3) * 2;
#pragma unroll
                    for (int j = 0; j < 4; ++j) {
                        float v0 = acc[ms][i][j][h * 2 + 0] + bv;
                        float v1 = acc[ms][i][j][h * 2 + 1] + bv;
                        if (act) {
                            v0 = v0 / (1.f + expf(-v0));
                            v1 = v1 / (1.f + expf(-v1));
                        }
                        *(float2*)(dst + j * 8) = make_float2(v0, v1);
                    }
                }
            }
        }
}

// ---------------------------------------------------------------------------
// Launch sequence
// ---------------------------------------------------------------------------
extern "C" void kernel_launch(void* const* d_in, const int* in_sizes, int n_in,
                              void* d_out, int out_size)
{
    (void)in_sizes; (void)n_in; (void)out_size;
    const float* x      = (const float*)d_in[0];
    const float* offf   = (const float*)d_in[1];
    const float* weight = (const float*)d_in[2];
    const float* bias   = (const float*)d_in[3];
    const float* w1     = (const float*)d_in[4];
    const float* b1     = (const float*)d_in[5];
    const float* w2     = (const float*)d_in[6];
    const float* b2     = (const float*)d_in[7];
    const float* w3     = (const float*)d_in[8];
    const float* b3     = (const float*)d_in[9];
    float* out = (float*)d_out;

    cudaFuncSetAttribute(gemm_tc, cudaFuncAttributeMaxDynamicSharedMemorySize, SMEM_TOT);

    const int IMB = (NB * KDIM * HWSZ) / (256 * 8);
    dim3 g256(1, 32, NB);       // (256-row m-tiles, n-tiles, batch)
    dim3 g432(2, 32, NB);       // M=432 padded to 512

    convw_k<<<(1280 * KDIM) / 256, 256>>>(w1, w2, w3, weight);

    im2col_k<<<IMB, 256>>>(offf, 0);
    gemm_tc<<<g256, 256, SMEM_TOT>>>(0,    b1,   nullptr, 256, 1, DST_T1);

    im2col_k<<<IMB, 256>>>(nullptr, 1);
    gemm_tc<<<g256, 256, SMEM_TOT>>>(256,  b2,   nullptr, 256, 1, DST_T2);

    im2col_k<<<IMB, 256>>>(nullptr, 2);
    gemm_tc<<<g432, 256, SMEM_TOT>>>(512,  b3,   nullptr, 432, 0, DST_T3);

    sample_k<<<dim3(16, 144, NB), 256>>>(x);
    gemm_tc<<<g256, 256, SMEM_TOT>>>(1024, bias, out,     256, 0, DST_OUT);
}

// round 7
// speedup vs baseline: 5.3451x; 1.7058x over previous
#include <cuda_runtime.h>
#include <cuda_fp16.h>
#include <math.h>
#include <stdint.h>

#define NB    4
#define HWSZ  4096
#define KDIM  2304
#define NCH   (KDIM / 32)      // 72 k-chunks of 32

// ---------------------------------------------------------------------------
// Scratch (device globals)
// ---------------------------------------------------------------------------
__device__ float g_t1[NB * 256 * HWSZ];                 // fp32 activations
__device__ float g_t2[NB * 256 * HWSZ];
__device__ float g_t3[NB * 432 * HWSZ];
__device__ __half g_cols[(size_t)NB * KDIM * HWSZ];     // B fp16 plane (75.5MB)
__device__ __half g_wh[1280 * KDIM];                    // packed weights fp16

#define DST_T1  0
#define DST_T2  1
#define DST_T3  2
#define DST_OUT 3

// ---------------------------------------------------------------------------
// PTX helpers (family-common, valid on target sm_100)
// ---------------------------------------------------------------------------
static __device__ __forceinline__ uint32_t smem_u32(const void* p) {
    uint32_t a;
    asm("{ .reg .u64 t; cvta.to.shared.u64 t, %1; cvt.u32.u64 %0, t; }" : "=r"(a) : "l"(p));
    return a;
}
#define CP16(dst, src) \
    asm volatile("cp.async.cg.shared.global [%0], [%1], 16;" :: "r"(dst), "l"(src))
#define CP_COMMIT()  asm volatile("cp.async.commit_group;" ::: "memory")
#define CP_WAIT1()   asm volatile("cp.async.wait_group 1;" ::: "memory")
#define CP_WAIT0()   asm volatile("cp.async.wait_group 0;" ::: "memory")

#define LDSM_X4(r, addr) \
    asm volatile("ldmatrix.sync.aligned.m8n8.x4.shared.b16 {%0,%1,%2,%3}, [%4];" \
        : "=r"((r)[0]), "=r"((r)[1]), "=r"((r)[2]), "=r"((r)[3]) : "r"(addr))
#define LDSM_X2T(r, addr) \
    asm volatile("ldmatrix.sync.aligned.m8n8.x2.trans.shared.b16 {%0,%1}, [%2];" \
        : "=r"((r)[0]), "=r"((r)[1]) : "r"(addr))

#define MMA_F16(d, a, b) \
    asm volatile("mma.sync.aligned.m16n8k16.row.col.f32.f16.f16.f32 " \
        "{%0,%1,%2,%3}, {%4,%5,%6,%7}, {%8,%9}, {%0,%1,%2,%3};" \
        : "+f"((d)[0]), "+f"((d)[1]), "+f"((d)[2]), "+f"((d)[3]) \
        : "r"((a)[0]), "r"((a)[1]), "r"((a)[2]), "r"((a)[3]), "r"((b)[0]), "r"((b)[1]))

// ---------------------------------------------------------------------------
// Weight pre-convert: pack w1|w2|w3(padded to 512)|weight into fp16
// (1280 rows x 2304).
// ---------------------------------------------------------------------------
__global__ void convw_k(const float* __restrict__ w1, const float* __restrict__ w2,
                        const float* __restrict__ w3, const float* __restrict__ wm)
{
    int idx = blockIdx.x * 256 + threadIdx.x;       // 0 .. 1280*2304-1
    int row = idx / KDIM;
    int col = idx - row * KDIM;
    float v = 0.f;
    if (row < 256)       v = w1[row * KDIM + col];
    else if (row < 512)  v = w2[(row - 256) * KDIM + col];
    else if (row < 1024) { int r = row - 512; if (r < 432) v = w3[r * KDIM + col]; }
    else                 v = wm[(row - 1024) * KDIM + col];
    g_wh[idx] = __float2half_rn(v);
}

// ---------------------------------------------------------------------------
// im2col -> fp16 plane. One thread: one (b,cin,ki,y) source row segment of 8
// outputs for ALL 3 kj taps (vector loads, 3 x 16B stores).
// src: 0=ext fp32, 1=g_t1, 2=g_t2
// ---------------------------------------------------------------------------
__global__ void im2col_k(const float* __restrict__ ext, int srcsel)
{
    const float* src = (srcsel == 1) ? g_t1 : (srcsel == 2) ? g_t2 : ext;
    int idx  = blockIdx.x * 256 + threadIdx.x;  // NB*256*3*64*8 threads
    int xc   = idx & 7;
    int x0   = xc * 8;
    int y    = (idx >> 3) & 63;
    int rest = idx >> 9;
    int ki   = rest % 3;
    int t2   = rest / 3;
    int cin  = t2 & 255;
    int b    = t2 >> 8;
    int ys   = y + ki - 1;

    float v[10];
    if ((unsigned)ys < 64u) {
        const float* row = src + ((size_t)(b * 256 + cin) << 12) + (ys << 6);
        *(float4*)(v + 1) = *(const float4*)(row + x0);
        *(float4*)(v + 5) = *(const float4*)(row + x0 + 4);
        v[0] = (x0 > 0)  ? row[x0 - 1] : 0.f;
        v[9] = (x0 < 56) ? row[x0 + 8] : 0.f;
    } else {
#pragma unroll
        for (int e = 0; e < 10; ++e) v[e] = 0.f;
    }

    __half h[10];
#pragma unroll
    for (int e = 0; e < 10; ++e) h[e] = __float2half_rn(v[e]);

    const size_t obase = ((size_t)(b * KDIM + cin * 9 + ki * 3) << 12) + (y << 6) + x0;
#pragma unroll
    for (int kj = 0; kj < 3; ++kj) {
        __half o[8];
#pragma unroll
        for (int e = 0; e < 8; ++e) o[e] = h[kj + e];
        *(uint4*)&g_cols[obase + ((size_t)kj << 12)] = *(uint4*)o;
    }
}

// ---------------------------------------------------------------------------
// Deformable bilinear sampling -> fp16 plane
// ---------------------------------------------------------------------------
__global__ void sample_k(const float* __restrict__ x)
{
    const int b  = blockIdx.z;
    const int gk = blockIdx.y;
    const int g  = gk / 9;
    const int k  = gk - g * 9;
    const int ki = k / 3;
    const int kj = k - ki * 3;
    const int p  = blockIdx.x * 256 + threadIdx.x;
    const int y  = p >> 6;
    const int xx = p & 63;

    const float* t3b = g_t3 + (size_t)b * 432 * HWSZ;
    const float dy = t3b[(g * 18 + 2 * k) * HWSZ + p];
    const float dx = t3b[(g * 18 + 2 * k + 1) * HWSZ + p];
    float mv       = t3b[(288 + g * 9 + k) * HWSZ + p];
    mv = 1.f / (1.f + expf(-mv));

    const float ys  = (float)(y - 1 + ki) + dy;
    const float xs  = (float)(xx - 1 + kj) + dx;
    const float y0f = floorf(ys);
    const float x0f = floorf(xs);
    const float wy  = ys - y0f;
    const float wx  = xs - x0f;
    const int y0 = (int)y0f;
    const int x0 = (int)x0f;

    const bool vy0 = ((unsigned)y0       < 64u);
    const bool vy1 = ((unsigned)(y0 + 1) < 64u);
    const bool vx0 = ((unsigned)x0       < 64u);
    const bool vx1 = ((unsigned)(x0 + 1) < 64u);

    float w00 = (vy0 && vx0) ? (1.f - wy) * (1.f - wx) * mv : 0.f;
    float w01 = (vy0 && vx1) ? (1.f - wy) * wx         * mv : 0.f;
    float w10 = (vy1 && vx0) ? wy * (1.f - wx)         * mv : 0.f;
    float w11 = (vy1 && vx1) ? wy * wx                 * mv : 0.f;

    const int yc0 = min(max(y0, 0), 63);
    const int yc1 = min(max(y0 + 1, 0), 63);
    const int xc0 = min(max(x0, 0), 63);
    const int xc1 = min(max(x0 + 1, 0), 63);
    const int i00 = (yc0 << 6) + xc0;
    const int i01 = (yc0 << 6) + xc1;
    const int i10 = (yc1 << 6) + xc0;
    const int i11 = (yc1 << 6) + xc1;

    const float* xb = x + ((size_t)b * 256 + g * 16) * HWSZ;
    const size_t base = ((size_t)b * KDIM + (g * 16) * 9 + k) * HWSZ + p;

#pragma unroll
    for (int c = 0; c < 16; ++c) {
        const float* xc = xb + c * HWSZ;
        float v = w00 * xc[i00] + w01 * xc[i01] + w10 * xc[i10] + w11 * xc[i11];
        g_cols[base + (size_t)c * 9 * HWSZ] = __float2half_rn(v);
    }
}

// ---------------------------------------------------------------------------
// HMMA fp16 GEMM, CTA tile 256m x 128n x 32k (2 m-subtiles share the B tile):
//   C[b][m][n] = sum_k W[aoff+m][k] * cols[b][k][n] + bias[m]  (+SiLU)
// 8 warps (2m x 4n per msub), warp tile 64x32, mma m16n8k16 fp16,
// cp.async double buffer; B read ONCE per stage.
// SMEM: A [buf][msub][128m][80B], B [buf][32k][272B]
// ---------------------------------------------------------------------------
#define A_MS   10240     // 128*80
#define A_BUF  20480     // 2 msub
#define B_ST   40960     // after 2 A bufs
#define B_BUF  8704      // 32*272
#define SMEM_TOT (B_ST + 2 * B_BUF)   // 58368

__global__ void __launch_bounds__(256, 1)
gemm_tc(int aoff, const float* __restrict__ bias, float* __restrict__ extC,
        int M, int act, int dstsel)
{
    extern __shared__ char smem[];
    const uint32_t sb = smem_u32(smem);
    const int tid  = threadIdx.x;
    const int lane = tid & 31;
    const int wid  = tid >> 5;
    const int wm   = wid >> 2;          // 0..1
    const int wn   = wid & 3;           // 0..3
    const int m0   = blockIdx.x * 256;
    const int n0   = blockIdx.y * 128;
    const int b    = blockIdx.z;

    float* C = (dstsel == DST_T1) ? g_t1
             : (dstsel == DST_T2) ? g_t2
             : (dstsel == DST_T3) ? g_t3 : extC;
    float* Cb = C + (size_t)b * M * HWSZ;

    const __half* gA = g_wh + (size_t)(aoff + m0) * KDIM;
    const __half* gB = g_cols + (size_t)b * KDIM * HWSZ;

    // cp.async mappings
    const int arow0 = tid >> 2, akc = tid & 3;     // A: 64 rows x 4 chunks
    const int bk0   = tid >> 4, bnc = tid & 15;    // B: 16 k x 16 chunks

    auto issue = [&](int t, int buf) {
        const int k0 = t * 32;
#pragma unroll
        for (int ms = 0; ms < 2; ++ms)
#pragma unroll
            for (int it = 0; it < 2; ++it) {
                int m = arow0 + it * 64;
                uint32_t dst = sb + buf * A_BUF + ms * A_MS + m * 80 + akc * 16;
                CP16(dst, gA + (size_t)(ms * 128 + m) * KDIM + k0 + akc * 8);
            }
#pragma unroll
        for (int it = 0; it < 2; ++it) {
            int kk = bk0 + it * 16;
            uint32_t dst = sb + B_ST + buf * B_BUF + kk * 272 + bnc * 16;
            CP16(dst, gB + (size_t)(k0 + kk) * HWSZ + n0 + bnc * 8);
        }
        CP_COMMIT();
    };

    float acc[2][4][4][4];
#pragma unroll
    for (int ms = 0; ms < 2; ++ms)
#pragma unroll
        for (int i = 0; i < 4; ++i)
#pragma unroll
            for (int j = 0; j < 4; ++j)
#pragma unroll
                for (int q = 0; q < 4; ++q) acc[ms][i][j][q] = 0.f;

    issue(0, 0);

    for (int t = 0; t < NCH; ++t) {
        const int buf = t & 1;
        const bool more = (t + 1 < NCH);
        if (more) { issue(t + 1, buf ^ 1); CP_WAIT1(); }
        else      { CP_WAIT0(); }
        __syncthreads();

        const uint32_t aB = sb + buf * A_BUF;
        const uint32_t bB = sb + B_ST + buf * B_BUF;
#pragma unroll
        for (int s = 0; s < 2; ++s) {
            uint32_t bf[4][2];
            const uint32_t brow = (uint32_t)(s * 16 + (lane & 15));
#pragma unroll
            for (int j = 0; j < 4; ++j)
                LDSM_X2T(bf[j], bB + brow * 272 + (uint32_t)(wn * 64 + j * 16));

            const uint32_t arow = (uint32_t)(wm * 64 + (lane & 15));
            const uint32_t acol = (uint32_t)(s * 32 + (lane >> 4) * 16);
#pragma unroll
            for (int ms = 0; ms < 2; ++ms) {
                uint32_t ah[4][4];
#pragma unroll
                for (int i = 0; i < 4; ++i)
                    LDSM_X4(ah[i], aB + ms * A_MS + (arow + i * 16) * 80 + acol);
#pragma unroll
                for (int i = 0; i < 4; ++i)
#pragma unroll
                    for (int j = 0; j < 4; ++j)
                        MMA_F16(acc[ms][i][j], ah[i], bf[j]);
            }
        }
        __syncthreads();
    }

    // epilogue: bias (+SiLU), float2 stores
#pragma unroll
    for (int ms = 0; ms < 2; ++ms)
#pragma unroll
        for (int i = 0; i < 4; ++i) {
            const int r0 = m0 + ms * 128 + wm * 64 + i * 16 + (lane >> 2);
#pragma unroll
            for (int h = 0; h < 2; ++h) {
                const int r = r0 + h * 8;
                if (r < M) {
                    const float bv = bias[r];
                    float* dst = Cb + (size_t)r * HWSZ + n0 + wn * 32 + (lane & 3) * 2;
#pragma unroll
                    for (int j = 0; j < 4; ++j) {
                        float v0 = acc[ms][i][j][h * 2 + 0] + bv;
                        float v1 = acc[ms][i][j][h * 2 + 1] + bv;
                        if (act) {
                            v0 = v0 / (1.f + expf(-v0));
                            v1 = v1 / (1.f + expf(-v1));
                        }
                        *(float2*)(dst + j * 8) = make_float2(v0, v1);
                    }
                }
            }
        }
}

// ---------------------------------------------------------------------------
// Launch sequence
// ---------------------------------------------------------------------------
extern "C" void kernel_launch(void* const* d_in, const int* in_sizes, int n_in,
                              void* d_out, int out_size)
{
    (void)in_sizes; (void)n_in; (void)out_size;
    const float* x      = (const float*)d_in[0];
    const float* offf   = (const float*)d_in[1];
    const float* weight = (const float*)d_in[2];
    const float* bias   = (const float*)d_in[3];
    const float* w1     = (const float*)d_in[4];
    const float* b1     = (const float*)d_in[5];
    const float* w2     = (const float*)d_in[6];
    const float* b2     = (const float*)d_in[7];
    const float* w3     = (const float*)d_in[8];
    const float* b3     = (const float*)d_in[9];
    float* out = (float*)d_out;

    cudaFuncSetAttribute(gemm_tc, cudaFuncAttributeMaxDynamicSharedMemorySize, SMEM_TOT);

    const int IMB = (NB * 256 * 3 * 64 * 8) / 256;   // 6144 blocks
    dim3 g256(1, 32, NB);       // (256-row m-tiles, n-tiles, batch)
    dim3 g432(2, 32, NB);       // M=432 padded to 512

    convw_k<<<(1280 * KDIM) / 256, 256>>>(w1, w2, w3, weight);

    im2col_k<<<IMB, 256>>>(offf, 0);
    gemm_tc<<<g256, 256, SMEM_TOT>>>(0,    b1,   nullptr, 256, 1, DST_T1);

    im2col_k<<<IMB, 256>>>(nullptr, 1);
    gemm_tc<<<g256, 256, SMEM_TOT>>>(256,  b2,   nullptr, 256, 1, DST_T2);

    im2col_k<<<IMB, 256>>>(nullptr, 2);
    gemm_tc<<<g432, 256, SMEM_TOT>>>(512,  b3,   nullptr, 432, 0, DST_T3);

    sample_k<<<dim3(16, 144, NB), 256>>>(x);
    gemm_tc<<<g256, 256, SMEM_TOT>>>(1024, bias, out,     256, 0, DST_OUT);
}